// round 11
// baseline (speedup 1.0000x reference)
#include <cuda_runtime.h>
#include <cstdint>

#define NH       4096
#define NH4      1024
#define NSTAGE   252                // 63 RK4 steps * 4 stages
#define NOUT     128
#define CMB4     1152

#define GRID     147
#define NW       14
#define NTHREADS 448
#define RPB      28                 // rows per CTA (4 per warp-pair)
#define SW       13                 // weight rows in SMEM

// smem: [13 Wf rows = 212992][v 16384][pbuf 224][pad][dt 256] = 229856 < 232448
#define OFF_VSM    212992
#define OFF_PBUF   229376
#define OFF_DT     229600
#define SMEM_BYTES 229856

__device__ __align__(16) float gV[2][4128];   // rows 0..4115 used (147*28)
__device__ __align__(16) float gHn[4128];
__device__ unsigned g_arrive;                 // single monotonic barrier counter

__device__ __forceinline__ unsigned bar_arrive() {
    __syncthreads();
    unsigned target = 0;
    if (threadIdx.x == 0) {
        unsigned old;
        asm volatile("atom.add.release.gpu.u32 %0, [%1], 1;"
                     : "=r"(old) : "l"(&g_arrive) : "memory");
        target = old - old % GRID + GRID;
    }
    return target;
}

__device__ __forceinline__ void bar_wait(unsigned target) {
    if (threadIdx.x == 0) {
        unsigned cur;
        do {
            asm volatile("ld.acquire.gpu.u32 %0, [%1];"
                         : "=r"(cur) : "l"(&g_arrive) : "memory");
        } while ((int)(cur - target) < 0);
    }
    __syncthreads();
}

__device__ __forceinline__ float warp_sum(float v) {
    #pragma unroll
    for (int o = 16; o; o >>= 1) v += __shfl_xor_sync(0xffffffffu, v, o);
    return v;
}

#define FMA4(A, Q, B) \
    { (A).x = fmaf((Q).x, (B).x, (A).x); (A).y = fmaf((Q).y, (B).y, (A).y); \
      (A).z = fmaf((Q).z, (B).z, (A).z); (A).w = fmaf((Q).w, (B).w, (A).w); }

__global__ void __launch_bounds__(NTHREADS, 1)
ode_rnn_kernel(const float* __restrict__ x,
               const float* __restrict__ h0,
               const float* __restrict__ t,
               const float* __restrict__ Wf,
               const float* __restrict__ bf,
               const float* __restrict__ Wi,
               const float* __restrict__ bi,
               const float* __restrict__ Wo,
               const float* __restrict__ bo,
               float* __restrict__ out)
{
    extern __shared__ char smem[];
    float4* wsm   = (float4*)smem;
    float4* vsm4  = (float4*)(smem + OFF_VSM);
    float*  psm   = (float*)(smem + OFF_PBUF);   // [7 pairs][2 kh][4 rows]
    float*  dtbuf = (float*)(smem + OFF_DT);

    const int tid  = threadIdx.x;
    const int w    = tid >> 5;
    const int lane = tid & 31;
    const int base = blockIdx.x * RPB;

    const int pair = w >> 1;
    const int kh   = w & 1;
    const int cb   = 16 * kh;                   // first chunk of this warp's K-half
    const bool p6  = (pair == 6);
    const int r0   = base + 4 * pair;           // pair rows r0..r0+3

    const float4* Wf4 = (const float4*)Wf;

    // SMEM weight rows: slot s<12 -> row base+4*(s/2)+(s%2); slot 12 -> base+24
    for (int idx = tid; idx < SW * NH4; idx += NTHREADS) {
        int slot   = idx >> 10;
        int within = idx & 1023;
        int lr     = (slot < 12) ? (4 * (slot >> 1) + (slot & 1)) : 24;
        int gr     = min(base + lr, NH - 1);
        wsm[idx]   = __ldg(Wf4 + (size_t)gr * NH4 + within);
    }
    if (tid < NSTAGE / 4) dtbuf[tid] = __ldg(t + tid + 1) - __ldg(t + tid);

    // per-pair weight sources
    const float4* wsA = wsm + (size_t)(p6 ? 12 : 2 * pair)     * NH4;  // row r0   (SMEM)
    const float4* wsB = wsm + (size_t)(p6 ? 12 : 2 * pair + 1) * NH4;  // row r0+1 (SMEM, q<=5)
    const float4* p2  = Wf4 + (size_t)min(r0 + (p6 ? 1 : 2), NH - 1) * NH4;  // L2 stream 1
    const float4* p3  = Wf4 + (size_t)min(r0 + (p6 ? 2 : 3), NH - 1) * NH4;  // L2 stream 2
    const float4* p4  = Wf4 + (size_t)min(r0 + 3,            NH - 1) * NH4;  // L2 stream 3 (p6)

    // register caches (pairs 0..5): chunks cb..cb+6 of both L2 rows
    float4 cC[7], cD[7];
    if (!p6) {
        #pragma unroll
        for (int k = 0; k < 7; ++k) {
            cC[k] = __ldg(p2 + lane + 32 * (cb + k));
            cD[k] = __ldg(p3 + lane + 32 * (cb + k));
        }
    }

    // RK4 state: kh==0 warps, lanes 0..3 own rows r0..r0+3
    const int myr = min(r0 + (lane & 3), NH - 1);
    float hh = 0.f, bfv = 0.f;
    if (kh == 0 && lane < 4) {
        hh  = __ldg(h0 + myr);
        bfv = __ldg(bf + myr);
        gV[0][r0 + lane] = hh;
    }

    float4 rc[4], rd[4], re[4];

    unsigned tgt = bar_arrive();
    if (!p6) {
        #pragma unroll
        for (int j = 0; j < 4; ++j) {
            rc[j] = __ldg(p2 + lane + 32 * (cb + 7 + j));
            rd[j] = __ldg(p3 + lane + 32 * (cb + 7 + j));
        }
    } else {
        #pragma unroll
        for (int j = 0; j < 4; ++j) {
            rc[j] = __ldg(p2 + lane + 32 * (cb + j));
            rd[j] = __ldg(p3 + lane + 32 * (cb + j));
            re[j] = __ldg(p4 + lane + 32 * (cb + j));
        }
    }
    bar_wait(tgt);

    int p = 0;
    float k1 = 0.f, k2 = 0.f, k3 = 0.f;

    #pragma unroll 1
    for (int sg = 0; sg < NSTAGE; ++sg) {
        const float dt = dtbuf[sg >> 2];
        const int   u  = sg & 3;

        // ---- v fill, batched MLP=3 ----
        {
            const float4* src = (const float4*)gV[p];
            float4 t0 = __ldcg(src + tid);
            float4 t1 = __ldcg(src + tid + NTHREADS);
            float4 t2;
            const bool g3 = tid < (NH4 - 2 * NTHREADS);   // tid < 128
            if (g3) t2 = __ldcg(src + tid + 2 * NTHREADS);
            vsm4[tid] = t0;
            vsm4[tid + NTHREADS] = t1;
            if (g3) vsm4[tid + 2 * NTHREADS] = t2;
        }
        __syncthreads();

        float4 A0 = make_float4(0.f,0.f,0.f,0.f);
        float4 A1 = A0, A2 = A0, A3 = A0;

        if (!p6) {
            #pragma unroll
            for (int k = 0; k < 7; ++k) {
                const int i = lane + 32 * (cb + k);
                float4 b = vsm4[i];
                FMA4(A0, wsA[i], b);
                FMA4(A1, wsB[i], b);
                FMA4(A2, cC[k], b);
                FMA4(A3, cD[k], b);
            }
            #pragma unroll
            for (int k = 7; k < 16; ++k) {
                const int i = lane + 32 * (cb + k);
                const int j = (k - 7) & 3;
                float4 b  = vsm4[i];
                float4 q2 = rc[j];
                float4 q3 = rd[j];
                if (k < 12) { rc[j] = __ldg(p2 + i + 128);    // chunk k+4
                              rd[j] = __ldg(p3 + i + 128); }
                FMA4(A0, wsA[i], b);
                FMA4(A1, wsB[i], b);
                FMA4(A2, q2, b);
                FMA4(A3, q3, b);
            }
        } else {
            #pragma unroll
            for (int k = 0; k < 16; ++k) {
                const int i = lane + 32 * (cb + k);
                const int j = k & 3;
                float4 b  = vsm4[i];
                float4 q2 = rc[j];
                float4 q3 = rd[j];
                float4 q4 = re[j];
                if (k < 12) { rc[j] = __ldg(p2 + i + 128);
                              rd[j] = __ldg(p3 + i + 128);
                              re[j] = __ldg(p4 + i + 128); }
                FMA4(A0, wsA[i], b);
                FMA4(A1, q2, b);
                FMA4(A2, q3, b);
                FMA4(A3, q4, b);
            }
        }

        // ---- fold 4 partials: rows r0,r0+1 -> m halves; rows r0+2,r0+3 -> n ----
        {
            const float s0 = (A0.x + A0.y) + (A0.z + A0.w);
            const float s1 = (A1.x + A1.y) + (A1.z + A1.w);
            const float s2 = (A2.x + A2.y) + (A2.z + A2.w);
            const float s3 = (A3.x + A3.y) + (A3.z + A3.w);
            const float a0 = s0 + __shfl_xor_sync(0xffffffffu, s0, 16);
            const float a1 = s1 + __shfl_xor_sync(0xffffffffu, s1, 16);
            const float a2 = s2 + __shfl_xor_sync(0xffffffffu, s2, 16);
            const float a3 = s3 + __shfl_xor_sync(0xffffffffu, s3, 16);
            float m = (lane & 16) ? a1 : a0;
            float n = (lane & 16) ? a3 : a2;
            #pragma unroll
            for (int o = 8; o; o >>= 1) {
                m += __shfl_xor_sync(0xffffffffu, m, o);
                n += __shfl_xor_sync(0xffffffffu, n, o);
            }
            float* pb = psm + pair * 8 + kh * 4;
            if (lane == 0)       { pb[0] = m; pb[2] = n; }
            else if (lane == 16) { pb[1] = m; pb[3] = n; }
        }
        __syncthreads();

        // ---- RK4 (kh==0 warps, lanes 0..3) + publish ----
        if (kh == 0 && lane < 4) {
            const float z = psm[pair * 8 + lane] + psm[pair * 8 + 4 + lane];
            const float kk = tanhf(z + bfv);
            float vn;
            const float half_dt = 0.5f * dt;
            if (u == 0)      { k1 = kk; vn = hh + half_dt * kk; }
            else if (u == 1) { k2 = kk; vn = hh + half_dt * kk; }
            else if (u == 2) { k3 = kk; vn = hh + dt * kk; }
            else {
                hh = hh + (dt * (1.0f / 6.0f)) * (k1 + 2.0f * k2 + 2.0f * k3 + kk);
                vn = hh;
            }
            gV[p ^ 1][r0 + lane] = vn;
        }

        // arrive, window-prefetch next stage's rings, wait
        tgt = bar_arrive();
        if (!p6) {
            #pragma unroll
            for (int j = 0; j < 4; ++j) {
                rc[j] = __ldg(p2 + lane + 32 * (cb + 7 + j));
                rd[j] = __ldg(p3 + lane + 32 * (cb + 7 + j));
            }
        } else {
            #pragma unroll
            for (int j = 0; j < 4; ++j) {
                rc[j] = __ldg(p2 + lane + 32 * (cb + j));
                rd[j] = __ldg(p3 + lane + 32 * (cb + j));
                re[j] = __ldg(p4 + lane + 32 * (cb + j));
            }
        }
        bar_wait(tgt);
        p ^= 1;
    }
    // hT in gV[p]

    // ---- i2h: h_new = tanh(W_i2h @ [x; hT] + b_i2h)  (warp w: rows 2w, 2w+1) ----
    {
        const float4* src = (const float4*)gV[p];
        for (int i = tid; i < NH4; i += NTHREADS) vsm4[i] = __ldcg(src + i);
        __syncthreads();

        const int rA  = base + 2 * w;
        const int cAi = min(rA,     NH - 1);
        const int cBi = min(rA + 1, NH - 1);
        const float4* Wi4 = (const float4*)Wi;
        const float4* qA  = Wi4 + (size_t)cAi * CMB4;
        const float4* qB  = Wi4 + (size_t)cBi * CMB4;
        const float4* x4  = (const float4*)x;

        float4 A0 = make_float4(0.f,0.f,0.f,0.f);
        float4 A1 = A0;
        #pragma unroll
        for (int jj = 0; jj < 4; ++jj) {
            const int i = lane + 32 * jj;
            float4 b = __ldg(x4 + i);
            FMA4(A0, __ldg(qA + i), b);
            FMA4(A1, __ldg(qB + i), b);
        }
        #pragma unroll 4
        for (int k = 0; k < 32; ++k) {
            const int i = lane + 32 * k;
            float4 b = vsm4[i];
            FMA4(A0, __ldg(qA + 128 + i), b);
            FMA4(A1, __ldg(qB + 128 + i), b);
        }
        const float zA = warp_sum((A0.x + A0.y) + (A0.z + A0.w));
        const float zB = warp_sum((A1.x + A1.y) + (A1.z + A1.w));

        if (lane == 0 && rA < NH) {
            const float hnA = tanhf(zA + __ldg(bi + cAi));
            const float hnB = tanhf(zB + __ldg(bi + cBi));
            *(float2*)(&gHn[rA])        = make_float2(hnA, hnB);
            *(float2*)(&out[NOUT + rA]) = make_float2(hnA, hnB);
        }
    }
    tgt = bar_arrive();
    bar_wait(tgt);

    // ---- h2o: out[0..127] (CTA cb<128, warp 0) ----
    if (blockIdx.x < NOUT && w == 0) {
        const int cb2 = blockIdx.x;
        const float4* pWo = (const float4*)Wo + (size_t)cb2 * NH4;
        const float4* hv  = (const float4*)gHn;
        float4 A = make_float4(0.f,0.f,0.f,0.f);
        #pragma unroll 4
        for (int k = 0; k < 32; ++k) {
            const int i = lane + 32 * k;
            FMA4(A, __ldg(pWo + i), __ldcg(hv + i));
        }
        const float z = warp_sum((A.x + A.y) + (A.z + A.w));
        if (lane == 0) out[cb2] = z + __ldg(bo + cb2);
    }
}

extern "C" void kernel_launch(void* const* d_in, const int* in_sizes, int n_in,
                              void* d_out, int out_size)
{
    const float* x   = (const float*)d_in[0];
    const float* h0  = (const float*)d_in[1];
    const float* t   = (const float*)d_in[2];
    const float* Wf  = (const float*)d_in[3];
    const float* bf  = (const float*)d_in[4];
    const float* Wi  = (const float*)d_in[5];
    const float* bi  = (const float*)d_in[6];
    const float* Wo  = (const float*)d_in[7];
    const float* bo  = (const float*)d_in[8];
    float* out = (float*)d_out;

    cudaFuncSetAttribute(ode_rnn_kernel,
                         cudaFuncAttributeMaxDynamicSharedMemorySize, SMEM_BYTES);
    ode_rnn_kernel<<<GRID, NTHREADS, SMEM_BYTES>>>(x, h0, t, Wf, bf, Wi, bi, Wo, bo, out);
}